// round 16
// baseline (speedup 1.0000x reference)
#include <cuda_runtime.h>
#include <cuda_bf16.h>
#include <cstddef>
#include <cstdint>

// x[64,512,128] @ Wx[128,1024] + b -> XP (in d_out); then
// h_t = tanh(xp_t + h_{t-1} @ Wh[1024,1024]); out[b,t,:] = h_t.
#define BB 64
#define TT 512
#define DD 128
#define HH 1024

typedef unsigned long long ull;

__device__ __forceinline__ ull pk2(float lo, float hi) {
    ull r; asm("mov.b64 %0, {%1, %2};" : "=l"(r) : "f"(lo), "f"(hi)); return r;
}
__device__ __forceinline__ float2 upk2(ull v) {
    float lo, hi; asm("mov.b64 {%0, %1}, %2;" : "=f"(lo), "=f"(hi) : "l"(v));
    return make_float2(lo, hi);
}
__device__ __forceinline__ ull ffma2(ull a, ull b, ull c) {
    ull d; asm("fma.rn.f32x2 %0, %1, %2, %3;" : "=l"(d) : "l"(a), "l"(b), "l"(c));
    return d;
}
__device__ __forceinline__ int ld_acq(const int* p) {
    int v; asm volatile("ld.acquire.gpu.global.s32 %0, [%1];" : "=r"(v) : "l"(p));
    return v;
}
__device__ __forceinline__ void red_rel_add1(int* p) {
    asm volatile("red.release.gpu.global.add.s32 [%0], 1;" :: "l"(p) : "memory");
}
__device__ __forceinline__ uint32_t smem_u32(const void* p) {
    uint32_t a;
    asm("{ .reg .u64 t; cvta.to.shared.u64 t, %1; cvt.u32.u64 %0, t; }"
        : "=r"(a) : "l"(p));
    return a;
}
__device__ __forceinline__ float fast_tanh(float x) {
    x = fminf(fmaxf(x, -15.f), 15.f);
    float e = __expf(x + x);
    return __fdividef(e - 1.f, e + 1.f);
}
__device__ __forceinline__ uint32_t pack_bf2(float a, float b) {
    __nv_bfloat162 v = __floats2bfloat162_rn(a, b);
    return *(uint32_t*)&v;
}

// warp-level MMA (sm_80 PTX; no arch-suffix features)
__device__ __forceinline__ void mma16816(
    float& d0, float& d1, float& d2, float& d3,
    uint32_t a0, uint32_t a1, uint32_t a2, uint32_t a3,
    uint32_t b0, uint32_t b1)
{
    asm volatile(
        "mma.sync.aligned.m16n8k16.row.col.f32.bf16.bf16.f32 "
        "{%0,%1,%2,%3}, {%4,%5,%6,%7}, {%8,%9}, {%0,%1,%2,%3};"
        : "+f"(d0), "+f"(d1), "+f"(d2), "+f"(d3)
        : "r"(a0), "r"(a1), "r"(a2), "r"(a3), "r"(b0), "r"(b1));
}
__device__ __forceinline__ void ldsm4(uint32_t& r0, uint32_t& r1,
                                      uint32_t& r2, uint32_t& r3, uint32_t a) {
    asm volatile("ldmatrix.sync.aligned.m8n8.x4.shared.b16 {%0,%1,%2,%3}, [%4];"
                 : "=r"(r0), "=r"(r1), "=r"(r2), "=r"(r3) : "r"(a));
}
__device__ __forceinline__ void ldsm2(uint32_t& r0, uint32_t& r1, uint32_t a) {
    asm volatile("ldmatrix.sync.aligned.m8n8.x2.shared.b16 {%0,%1}, [%2];"
                 : "=r"(r0), "=r"(r1) : "r"(a));
}

// ---------- global scratch ----------
__device__ __nv_bfloat16 g_hHI[2][BB][HH];   // h hi plane [b][k]
__device__ __nv_bfloat16 g_hLO[2][BB][HH];   // h lo plane
__device__ int g_flags[4][TT][8];            // (group, step, chunk) arrivals

// =====================================================================
// Kernel 1: XP = x @ Wx + b  -> d_out  (also resets flags)
// =====================================================================
__global__ __launch_bounds__(256) void xp_gemm(
    const float* __restrict__ x, const float* __restrict__ Wx,
    const float* __restrict__ bias, float* __restrict__ out)
{
    __shared__ float xs[64 * 68];
    __shared__ float ws[64 * 64];

    const int tid = threadIdx.x;
    if (blockIdx.x == 0 && blockIdx.y == 0) {
        int* f = &g_flags[0][0][0];
        for (int i = tid; i < 4 * TT * 8; i += 256) f[i] = 0;
    }

    const int m0 = blockIdx.x * 64;
    const int n0 = blockIdx.y * 64;
    const int ty = tid >> 4;
    const int tx = tid & 15;

    ull acc01[4] = {0ull, 0ull, 0ull, 0ull};
    ull acc23[4] = {0ull, 0ull, 0ull, 0ull};

    for (int k0 = 0; k0 < DD; k0 += 64) {
        __syncthreads();
        #pragma unroll
        for (int i = tid; i < 1024; i += 256) {
            int r = i >> 4, q = i & 15;
            ((float4*)xs)[r * 17 + q] =
                *(const float4*)&x[(size_t)(m0 + r) * DD + k0 + 4 * q];
        }
        #pragma unroll
        for (int i = tid; i < 1024; i += 256) {
            int r = i >> 4, q = i & 15;
            ((float4*)ws)[i] =
                *(const float4*)&Wx[(size_t)(k0 + r) * HH + n0 + 4 * q];
        }
        __syncthreads();

        #pragma unroll 8
        for (int kk = 0; kk < 64; kk++) {
            ulonglong2 wv = *(const ulonglong2*)&ws[kk * 64 + 4 * tx];
            #pragma unroll
            for (int i = 0; i < 4; i++) {
                float a = xs[(4 * ty + i) * 68 + kk];
                ull aa = pk2(a, a);
                acc01[i] = ffma2(aa, wv.x, acc01[i]);
                acc23[i] = ffma2(aa, wv.y, acc23[i]);
            }
        }
    }

    float4 bv = *(const float4*)&bias[n0 + 4 * tx];
    #pragma unroll
    for (int i = 0; i < 4; i++) {
        float2 p0 = upk2(acc01[i]);
        float2 p1 = upk2(acc23[i]);
        float4 r;
        r.x = p0.x + bv.x; r.y = p0.y + bv.y;
        r.z = p1.x + bv.z; r.w = p1.y + bv.w;
        *(float4*)&out[(size_t)(m0 + 4 * ty + i) * HH + n0 + 4 * tx] = r;
    }
}

// =====================================================================
// Kernel 2: persistent recurrence, TWO independent HMMA chains per SM.
// 128 CTAs x 512 thr. CTA cid: col slice j = cid&63 (16 cols; Wh hi/lo
// slice SHARED by both halves). half 0 (warps 0-7): group cid>>6,
// half 1 (warps 8-15): group cid>>6 + 2. Halves never sync each other.
// Per half: warp ks stages+consumes k-chunk ks (128 k x 16 batches),
// computes D16x16 = A(h hi/lo)[16][128] x B(WhT hi/lo)[16 n][128 k]
// via m16n8k16 bf16, 3 passes (fp32-faithful split).
// SMEM: Bhi/Blo [16][1040] bf16 (shared), Ahi/Alo [16][1040] x2 halves,
//       red [2 halves][8][16][18] float.
// Sync per half: flag poll (target 64 = 8 slices x 8 warps), two
// bar.sync(half+1, 256) per step (R5/R15 proven scheme).
// =====================================================================
#define LROW 1040
#define SM_BHI 0
#define SM_BLO (16 * LROW * 2)              /* 33280 */
#define SM_A   (2 * 16 * LROW * 2)          /* 66560: [half][hi/lo][16][LROW] */
#define A_HALF (2 * 16 * LROW * 2)          /* 66560 per half */
#define A_LO   (16 * LROW * 2)              /* +33280 within half */
#define SM_RED (SM_A + 2 * A_HALF)          /* 199680 */
#define RED_ROW 18
#define RED_HALF (8 * 16 * RED_ROW)         /* 2304 floats */
#define SMEM_BYTES (SM_RED + 2 * RED_HALF * 4)   /* 218112 */

__global__ __launch_bounds__(512, 1) void rnn_persist(
    float* __restrict__ out, const float* __restrict__ Wh)
{
    extern __shared__ char smem[];
    const int tid  = threadIdx.x;
    const int half = tid >> 8;
    const int tid2 = tid & 255;
    const int j    = blockIdx.x & 63;
    const int g    = (blockIdx.x >> 6) + 2 * half;
    const int B0   = 16 * g;
    const int C0   = 16 * j;
    const int jc   = j >> 3;               // chunk this slice feeds

    // one-time: B = WhT slice [16 n][1024 k] hi/lo bf16 (shared)
    for (int idx = tid; idx < 16 * HH; idx += 512) {
        int n = idx & 15, k = idx >> 4;
        float w = Wh[(size_t)k * HH + C0 + n];
        __nv_bfloat16 hi = __float2bfloat16(w);
        __nv_bfloat16 lo = __float2bfloat16(w - __bfloat162float(hi));
        *(__nv_bfloat16*)(smem + SM_BHI + (n * LROW + k) * 2) = hi;
        *(__nv_bfloat16*)(smem + SM_BLO + (n * LROW + k) * 2) = lo;
    }
    __syncthreads();    // only CTA-wide sync; halves independent after

    const int ks   = tid2 >> 5;     // local warp 0..7 = its k-chunk
    const int lane = tid & 31;

    char* smA = smem + SM_A + half * A_HALF;

    // ldmatrix source addresses
    const uint32_t sb = smem_u32(smem);
    const uint32_t aAhi = sb + SM_A + half * A_HALF +
        (uint32_t)(((lane & 15) * LROW + 128 * ks + 8 * (lane >> 4)) * 2);
    const uint32_t aAlo = aAhi + A_LO;
    const uint32_t aBhi = sb + SM_BHI +
        (uint32_t)(((lane & 7) * LROW + 128 * ks + 8 * ((lane >> 3) & 1)) * 2);
    const uint32_t aBlo = aBhi + SM_BLO;

    float* redh = (float*)(smem + SM_RED) + half * RED_HALF;

    const int eb = tid2 >> 4;       // epilogue batch 0..15
    const int ec = tid2 & 15;       // epilogue col 0..15

    for (int t = 0; t < TT; t++) {
        // prefetch xp (this thread's own element)
        size_t ob = ((size_t)(B0 + eb) * TT + t) * HH + C0 + ec;
        float xp = __ldcg(&out[ob]);

        if (t > 0) {
            const int pp = (t - 1) & 1;
            // wait for this chunk's 8 producer slices (64 warp-arrivals)
            const int* fl = &g_flags[g][t - 1][ks];
            while (ld_acq(fl) < 64) { }

            // stage own 128-k chunk of h hi/lo: [16 rows][128 k]
            {
                const __nv_bfloat16* sH = &g_hHI[pp][B0][0];
                const __nv_bfloat16* sL = &g_hLO[pp][B0][0];
                const int q = lane & 15;
                #pragma unroll
                for (int i = 0; i < 8; i++) {
                    int r = 2 * i + (lane >> 4);
                    int so = r * HH + 128 * ks;
                    uint4 vh = __ldcg((const uint4*)(sH + so) + q);
                    uint4 vl = __ldcg((const uint4*)(sL + so) + q);
                    int doff = (r * LROW + 128 * ks + 8 * q) * 2;
                    *(uint4*)(smA + doff)        = vh;
                    *(uint4*)(smA + A_LO + doff) = vl;
                }
            }
            __syncwarp();

            // compute: 8 ktiles x 2 ntiles x 3 MMAs
            float d[2][4];
            #pragma unroll
            for (int nt = 0; nt < 2; nt++)
                #pragma unroll
                for (int i = 0; i < 4; i++) d[nt][i] = 0.f;

            #pragma unroll 2
            for (int m = 0; m < 8; m++) {
                uint32_t ah0, ah1, ah2, ah3, al0, al1, al2, al3;
                ldsm4(ah0, ah1, ah2, ah3, aAhi + m * 32);
                ldsm4(al0, al1, al2, al3, aAlo + m * 32);
                #pragma unroll
                for (int nt = 0; nt < 2; nt++) {
                    uint32_t bh0, bh1, bl0, bl1;
                    uint32_t bo = (uint32_t)(nt * (8 * LROW * 2) + m * 32);
                    ldsm2(bh0, bh1, aBhi + bo);
                    ldsm2(bl0, bl1, aBlo + bo);
                    mma16816(d[nt][0], d[nt][1], d[nt][2], d[nt][3],
                             ah0, ah1, ah2, ah3, bh0, bh1);
                    mma16816(d[nt][0], d[nt][1], d[nt][2], d[nt][3],
                             ah0, ah1, ah2, ah3, bl0, bl1);
                    mma16816(d[nt][0], d[nt][1], d[nt][2], d[nt][3],
                             al0, al1, al2, al3, bh0, bh1);
                }
            }

            // write partials: D frag rows lane>>2 / +8, cols 2(lane&3)
            {
                const int r1 = lane >> 2;
                const int cc = 2 * (lane & 3);
                #pragma unroll
                for (int nt = 0; nt < 2; nt++) {
                    int nc = 8 * nt + cc;
                    *(float2*)&redh[(ks * 16 + r1) * RED_ROW + nc] =
                        make_float2(d[nt][0], d[nt][1]);
                    *(float2*)&redh[(ks * 16 + r1 + 8) * RED_ROW + nc] =
                        make_float2(d[nt][2], d[nt][3]);
                }
            }
        }
        // join this half's 8 warps
        asm volatile("bar.sync %0, 256;" :: "r"(half + 1) : "memory");

        // epilogue: reduce 8 chunks, add xp, tanh, publish
        float s = xp;
        if (t > 0) {
            #pragma unroll
            for (int q = 0; q < 8; q++)
                s += redh[(q * 16 + eb) * RED_ROW + ec];
        }
        float r = fast_tanh(s);
        const int hp = t & 1;
        {
            __nv_bfloat16 hv = __float2bfloat16(r);
            g_hHI[hp][B0 + eb][C0 + ec] = hv;
            g_hLO[hp][B0 + eb][C0 + ec] =
                __float2bfloat16(r - __bfloat162float(hv));
        }
        __syncwarp();
        if (lane == 0) red_rel_add1(&g_flags[g][t][jc]);
        out[ob] = r;   // off critical path

        // red reuse hazard fence for this half
        asm volatile("bar.sync %0, 256;" :: "r"(half + 1) : "memory");
    }
}

// =====================================================================
// Launch
// =====================================================================
extern "C" void kernel_launch(void* const* d_in, const int* in_sizes, int n_in,
                              void* d_out, int out_size)
{
    const float* x  = nullptr;
    const float* Wx = nullptr;
    const float* Wh = nullptr;
    const float* bv = nullptr;
    for (int i = 0; i < n_in; i++) {
        int s = in_sizes[i];
        if (s == BB * TT * DD)      x  = (const float*)d_in[i];
        else if (s == DD * HH)      Wx = (const float*)d_in[i];
        else if (s == HH * HH)      Wh = (const float*)d_in[i];
        else if (s == HH)           bv = (const float*)d_in[i];
    }
    float* out = (float*)d_out;

    static int configured = 0;
    if (!configured) {
        cudaFuncSetAttribute(rnn_persist,
                             cudaFuncAttributeMaxDynamicSharedMemorySize,
                             SMEM_BYTES);
        configured = 1;
    }

    dim3 g1((BB * TT) / 64, HH / 64);
    xp_gemm<<<g1, 256>>>(x, Wx, bv, out);

    rnn_persist<<<128, 512, SMEM_BYTES>>>(out, Wh);
}

// round 17
// speedup vs baseline: 1.3121x; 1.3121x over previous
#include <cuda_runtime.h>
#include <cuda_bf16.h>
#include <cstddef>
#include <cstdint>

// x[64,512,128] @ Wx[128,1024] + b -> XP (in d_out); then
// h_t = tanh(xp_t + h_{t-1} @ Wh[1024,1024]); out[b,t,:] = h_t.
#define BB 64
#define TT 512
#define DD 128
#define HH 1024

typedef unsigned long long ull;

__device__ __forceinline__ ull pk2(float lo, float hi) {
    ull r; asm("mov.b64 %0, {%1, %2};" : "=l"(r) : "f"(lo), "f"(hi)); return r;
}
__device__ __forceinline__ float2 upk2(ull v) {
    float lo, hi; asm("mov.b64 {%0, %1}, %2;" : "=f"(lo), "=f"(hi) : "l"(v));
    return make_float2(lo, hi);
}
__device__ __forceinline__ ull ffma2(ull a, ull b, ull c) {
    ull d; asm("fma.rn.f32x2 %0, %1, %2, %3;" : "=l"(d) : "l"(a), "l"(b), "l"(c));
    return d;
}
__device__ __forceinline__ int ld_acq(const int* p) {
    int v; asm volatile("ld.acquire.gpu.global.s32 %0, [%1];" : "=r"(v) : "l"(p));
    return v;
}
__device__ __forceinline__ void red_rel_add1(int* p) {
    asm volatile("red.release.gpu.global.add.s32 [%0], 1;" :: "l"(p) : "memory");
}
__device__ __forceinline__ uint32_t smem_u32(const void* p) {
    uint32_t a;
    asm("{ .reg .u64 t; cvta.to.shared.u64 t, %1; cvt.u32.u64 %0, t; }"
        : "=r"(a) : "l"(p));
    return a;
}
__device__ __forceinline__ float fast_tanh(float x) {
    x = fminf(fmaxf(x, -15.f), 15.f);
    float e = __expf(x + x);
    return __fdividef(e - 1.f, e + 1.f);
}
__device__ __forceinline__ uint32_t pack_bf2(float a, float b) {
    __nv_bfloat162 v = __floats2bfloat162_rn(a, b);
    return *(uint32_t*)&v;
}

// warp-level MMA (sm_80 PTX; no arch-suffix features)
__device__ __forceinline__ void mma16816(
    float& d0, float& d1, float& d2, float& d3,
    uint32_t a0, uint32_t a1, uint32_t a2, uint32_t a3,
    uint32_t b0, uint32_t b1)
{
    asm volatile(
        "mma.sync.aligned.m16n8k16.row.col.f32.bf16.bf16.f32 "
        "{%0,%1,%2,%3}, {%4,%5,%6,%7}, {%8,%9}, {%0,%1,%2,%3};"
        : "+f"(d0), "+f"(d1), "+f"(d2), "+f"(d3)
        : "r"(a0), "r"(a1), "r"(a2), "r"(a3), "r"(b0), "r"(b1));
}
__device__ __forceinline__ void ldsm4(uint32_t& r0, uint32_t& r1,
                                      uint32_t& r2, uint32_t& r3, uint32_t a) {
    asm volatile("ldmatrix.sync.aligned.m8n8.x4.shared.b16 {%0,%1,%2,%3}, [%4];"
                 : "=r"(r0), "=r"(r1), "=r"(r2), "=r"(r3) : "r"(a));
}
__device__ __forceinline__ void ldsm2(uint32_t& r0, uint32_t& r1, uint32_t a) {
    asm volatile("ldmatrix.sync.aligned.m8n8.x2.shared.b16 {%0,%1}, [%2];"
                 : "=r"(r0), "=r"(r1) : "r"(a));
}

// ---------- global scratch ----------
__device__ __nv_bfloat16 g_hHI[2][BB][HH];   // h hi plane [b][k]
__device__ __nv_bfloat16 g_hLO[2][BB][HH];   // h lo plane
__device__ int g_flags[4][TT][8];            // (group, step, chunk) arrivals

// =====================================================================
// Kernel 1: XP = x @ Wx + b  -> d_out  (also resets flags)
// =====================================================================
__global__ __launch_bounds__(256) void xp_gemm(
    const float* __restrict__ x, const float* __restrict__ Wx,
    const float* __restrict__ bias, float* __restrict__ out)
{
    __shared__ float xs[64 * 68];
    __shared__ float ws[64 * 64];

    const int tid = threadIdx.x;
    if (blockIdx.x == 0 && blockIdx.y == 0) {
        int* f = &g_flags[0][0][0];
        for (int i = tid; i < 4 * TT * 8; i += 256) f[i] = 0;
    }

    const int m0 = blockIdx.x * 64;
    const int n0 = blockIdx.y * 64;
    const int ty = tid >> 4;
    const int tx = tid & 15;

    ull acc01[4] = {0ull, 0ull, 0ull, 0ull};
    ull acc23[4] = {0ull, 0ull, 0ull, 0ull};

    for (int k0 = 0; k0 < DD; k0 += 64) {
        __syncthreads();
        #pragma unroll
        for (int i = tid; i < 1024; i += 256) {
            int r = i >> 4, q = i & 15;
            ((float4*)xs)[r * 17 + q] =
                *(const float4*)&x[(size_t)(m0 + r) * DD + k0 + 4 * q];
        }
        #pragma unroll
        for (int i = tid; i < 1024; i += 256) {
            int r = i >> 4, q = i & 15;
            ((float4*)ws)[i] =
                *(const float4*)&Wx[(size_t)(k0 + r) * HH + n0 + 4 * q];
        }
        __syncthreads();

        #pragma unroll 8
        for (int kk = 0; kk < 64; kk++) {
            ulonglong2 wv = *(const ulonglong2*)&ws[kk * 64 + 4 * tx];
            #pragma unroll
            for (int i = 0; i < 4; i++) {
                float a = xs[(4 * ty + i) * 68 + kk];
                ull aa = pk2(a, a);
                acc01[i] = ffma2(aa, wv.x, acc01[i]);
                acc23[i] = ffma2(aa, wv.y, acc23[i]);
            }
        }
    }

    float4 bv = *(const float4*)&bias[n0 + 4 * tx];
    #pragma unroll
    for (int i = 0; i < 4; i++) {
        float2 p0 = upk2(acc01[i]);
        float2 p1 = upk2(acc23[i]);
        float4 r;
        r.x = p0.x + bv.x; r.y = p0.y + bv.y;
        r.z = p1.x + bv.z; r.w = p1.y + bv.w;
        *(float4*)&out[(size_t)(m0 + 4 * ty + i) * HH + n0 + 4 * tx] = r;
    }
}

// =====================================================================
// Kernel 2: persistent recurrence via mma.sync (HMMA tensor pipe),
// with LOOP-INVARIANT B (Wh) FRAGMENTS HOISTED INTO REGISTERS.
// 128 CTAs x 256 thr (8 warps). CTA (g=bid>>5, j=bid&31): batches
// [16g,16g+16), cols [32j,32j+32); produces k-chunk j>>2.
// Warp ks stages+consumes k-chunk ks (128 k): D16x32 partial =
// A(h hi/lo bf16, [16][128]) x B(WhT hi/lo, [32 n][128 k]) via
// m16n8k16 bf16, 3 passes (hi*hi + hi*lo + lo*hi) = fp32-faithful.
// B fragments (8 ktiles x 4 ntiles x 2 regs x 2 planes = 128 regs)
// loaded ONCE before the t-loop; step compute = 16 ldsm4 + 96 HMMA.
// SMEM: Bhi/Blo [32][1040] bf16 (init only), Ahi/Alo [16][1040],
//       red[8][16][34] float. Sync: per-chunk flags (target 32),
//       two bar.sync per step (R15-proven).
// =====================================================================
#define LROW 1040
#define SM_BHI 0
#define SM_BLO (SM_BHI + 32 * LROW * 2)     /* 66560 */
#define SM_AHI (SM_BLO + 32 * LROW * 2)     /* 133120 */
#define SM_ALO (SM_AHI + 16 * LROW * 2)     /* 166400 */
#define SM_RED (SM_ALO + 16 * LROW * 2)     /* 199680 */
#define RED_ROW 34
#define SMEM_BYTES (SM_RED + 8 * 16 * RED_ROW * 4)   /* 217088 */

__global__ __launch_bounds__(256, 1) void rnn_persist(
    float* __restrict__ out, const float* __restrict__ Wh)
{
    extern __shared__ char smem[];
    const int tid  = threadIdx.x;
    const int g    = blockIdx.x >> 5;
    const int j    = blockIdx.x & 31;
    const int B0   = 16 * g;
    const int C0   = 32 * j;
    const int jc   = j >> 2;

    // one-time: B = WhT slice [32 n][1024 k] hi/lo bf16
    for (int idx = tid; idx < 32 * HH; idx += 256) {
        int n = idx & 31, k = idx >> 5;
        float w = Wh[(size_t)k * HH + C0 + n];
        __nv_bfloat16 hi = __float2bfloat16(w);
        __nv_bfloat16 lo = __float2bfloat16(w - __bfloat162float(hi));
        *(__nv_bfloat16*)(smem + SM_BHI + (n * LROW + k) * 2) = hi;
        *(__nv_bfloat16*)(smem + SM_BLO + (n * LROW + k) * 2) = lo;
    }
    __syncthreads();

    const int ks   = tid >> 5;      // warp = its k-chunk
    const int lane = tid & 31;

    // ldmatrix source addresses (k-chunk base folded in)
    const uint32_t sb = smem_u32(smem);
    const uint32_t aAhi = sb + SM_AHI +
        (uint32_t)(((lane & 15) * LROW + 128 * ks + 8 * (lane >> 4)) * 2);
    const uint32_t aAlo = aAhi + (SM_ALO - SM_AHI);
    const uint32_t aBhi = sb + SM_BHI +
        (uint32_t)(((lane & 7) * LROW + 128 * ks + 8 * ((lane >> 3) & 1)) * 2);
    const uint32_t aBlo = aBhi + (SM_BLO - SM_BHI);

    // hoist ALL loop-invariant B fragments into registers (128 regs)
    uint32_t Bh[8][4][2], Bl[8][4][2];
    #pragma unroll
    for (int m = 0; m < 8; m++) {
        #pragma unroll
        for (int nt = 0; nt < 4; nt++) {
            uint32_t bo = (uint32_t)(nt * (8 * LROW * 2) + m * 32);
            ldsm2(Bh[m][nt][0], Bh[m][nt][1], aBhi + bo);
            ldsm2(Bl[m][nt][0], Bl[m][nt][1], aBlo + bo);
        }
    }

    float* red = (float*)(smem + SM_RED);

    const int eb = tid >> 4;        // epilogue batch 0..15
    const int ec2 = 2 * (tid & 15); // epilogue col pair

    for (int t = 0; t < TT; t++) {
        // prefetch xp
        size_t ob = ((size_t)(B0 + eb) * TT + t) * HH + C0 + ec2;
        float2 xp = __ldcg((const float2*)&out[ob]);

        if (t > 0) {
            const int pp = (t - 1) & 1;
            // wait for this chunk's 4 producer CTAs (32 warp-arrivals)
            const int* fl = &g_flags[g][t - 1][ks];
            while (ld_acq(fl) < 32) { }

            // stage own 128-k chunk of h hi/lo: [16 rows][128 k]
            {
                const __nv_bfloat16* sH = &g_hHI[pp][B0][0];
                const __nv_bfloat16* sL = &g_hLO[pp][B0][0];
                const int q = lane & 15;
                #pragma unroll
                for (int i = 0; i < 8; i++) {
                    int r = 2 * i + (lane >> 4);
                    int so = r * HH + 128 * ks;
                    uint4 vh = __ldcg((const uint4*)(sH + so) + q);
                    uint4 vl = __ldcg((const uint4*)(sL + so) + q);
                    int doff = (r * LROW + 128 * ks + 8 * q) * 2;
                    *(uint4*)(smem + SM_AHI + doff) = vh;
                    *(uint4*)(smem + SM_ALO + doff) = vl;
                }
            }
            __syncwarp();

            // compute: 8 ktiles x (2 ldsm4 + 4 ntiles x 3 MMAs)
            float d[4][4];
            #pragma unroll
            for (int nt = 0; nt < 4; nt++)
                #pragma unroll
                for (int i = 0; i < 4; i++) d[nt][i] = 0.f;

            #pragma unroll 2
            for (int m = 0; m < 8; m++) {
                uint32_t ah0, ah1, ah2, ah3, al0, al1, al2, al3;
                ldsm4(ah0, ah1, ah2, ah3, aAhi + m * 32);
                ldsm4(al0, al1, al2, al3, aAlo + m * 32);
                #pragma unroll
                for (int nt = 0; nt < 4; nt++) {
                    mma16816(d[nt][0], d[nt][1], d[nt][2], d[nt][3],
                             ah0, ah1, ah2, ah3, Bh[m][nt][0], Bh[m][nt][1]);
                    mma16816(d[nt][0], d[nt][1], d[nt][2], d[nt][3],
                             ah0, ah1, ah2, ah3, Bl[m][nt][0], Bl[m][nt][1]);
                    mma16816(d[nt][0], d[nt][1], d[nt][2], d[nt][3],
                             al0, al1, al2, al3, Bh[m][nt][0], Bh[m][nt][1]);
                }
            }

            // write partials: D frag rows lane>>2 / +8, cols 2(lane&3)
            {
                const int r1 = lane >> 2;
                const int cc = 2 * (lane & 3);
                #pragma unroll
                for (int nt = 0; nt < 4; nt++) {
                    int nc = 8 * nt + cc;
                    *(float2*)&red[(ks * 16 + r1) * RED_ROW + nc] =
                        make_float2(d[nt][0], d[nt][1]);
                    *(float2*)&red[(ks * 16 + r1 + 8) * RED_ROW + nc] =
                        make_float2(d[nt][2], d[nt][3]);
                }
            }
        }
        __syncthreads();   // join: all partials in red

        // epilogue: reduce 8 chunks, add xp, tanh, publish
        float s0 = xp.x, s1 = xp.y;
        if (t > 0) {
            #pragma unroll
            for (int q = 0; q < 8; q++) {
                float2 rv = *(const float2*)&red[(q * 16 + eb) * RED_ROW + ec2];
                s0 += rv.x; s1 += rv.y;
            }
        }
        float r0 = fast_tanh(s0), r1 = fast_tanh(s1);
        const int hp = t & 1;
        {
            __nv_bfloat16 h0 = __float2bfloat16(r0);
            __nv_bfloat16 h1 = __float2bfloat16(r1);
            float l0 = r0 - __bfloat162float(h0);
            float l1 = r1 - __bfloat162float(h1);
            *(uint32_t*)&g_hHI[hp][B0 + eb][C0 + ec2] = pack_bf2(r0, r1);
            *(uint32_t*)&g_hLO[hp][B0 + eb][C0 + ec2] = pack_bf2(l0, l1);
        }
        __syncwarp();
        if (lane == 0) red_rel_add1(&g_flags[g][t][jc]);
        *(float2*)&out[ob] = make_float2(r0, r1);   // off critical path

        __syncthreads();   // red reuse hazard fence
    }
}

// =====================================================================
// Launch
// =====================================================================
extern "C" void kernel_launch(void* const* d_in, const int* in_sizes, int n_in,
                              void* d_out, int out_size)
{
    const float* x  = nullptr;
    const float* Wx = nullptr;
    const float* Wh = nullptr;
    const float* bv = nullptr;
    for (int i = 0; i < n_in; i++) {
        int s = in_sizes[i];
        if (s == BB * TT * DD)      x  = (const float*)d_in[i];
        else if (s == DD * HH)      Wx = (const float*)d_in[i];
        else if (s == HH * HH)      Wh = (const float*)d_in[i];
        else if (s == HH)           bv = (const float*)d_in[i];
    }
    float* out = (float*)d_out;

    static int configured = 0;
    if (!configured) {
        cudaFuncSetAttribute(rnn_persist,
                             cudaFuncAttributeMaxDynamicSharedMemorySize,
                             SMEM_BYTES);
        configured = 1;
    }

    dim3 g1((BB * TT) / 64, HH / 64);
    xp_gemm<<<g1, 256>>>(x, Wx, bv, out);

    rnn_persist<<<128, 256, SMEM_BYTES>>>(out, Wh);
}